// round 12
// baseline (speedup 1.0000x reference)
#include <cuda_runtime.h>
#include <cuda_fp16.h>

#define NN 100000
#define EE 1600000
#define FIN 100
#define D 64
#define GG 500
#define SCAN_T 512
#define SCAN_NB ((NN + SCAN_T - 1) / SCAN_T)
#define APAD 132

// ---------------- scratch (device globals; no allocs allowed) ----------------
__device__ float g_deg[NN];
__device__ int   g_cntn[NN];
__device__ int   g_ptr[NN + 1];
__device__ int   g_partials[SCAN_NB];
__device__ int2  g_csr[EE];        // packed {row, norm_bits}
__device__ float g_out0[NN * D];
__device__ uint4 g_hh[NN * 8];     // h fp16: 64 halves = 8 uint4 per row
__device__ float g_aggA[NN * D];
__device__ float g_aggB[NN * D];
__device__ float g_sums[GG * D];
__device__ float g_cnt[GG];
__device__ int g_is64_edge;
__device__ int g_is64_batch;

__device__ __forceinline__ int load_idx(const void* p, long long i, int is64) {
    return is64 ? (int)((const long long*)p)[i] : ((const int*)p)[i];
}

// ptr fixup inlined: final ptr(n) = g_ptr[n] + partials[n>>9]
__device__ __forceinline__ int ptr_of(int n) {
    return (n == NN) ? EE : g_ptr[n] + g_partials[n >> 9];
}

// ---------------- init: zero scratch + dtype detect (one kernel) -------------
__global__ void init_kernel(const int* ei, const int* bat) {
    int t = blockIdx.x * 256 + threadIdx.x;
    if (t < NN) { g_deg[t] = 0.f; g_cntn[t] = 0; }
    if (t < GG * D) g_sums[t] = 0.f;
    if (t < GG) g_cnt[t] = 0.f;
    if (blockIdx.x == 0 && threadIdx.x < 32) {
        int i = threadIdx.x;
        int nz_e = 0, nz_b = 0;
        for (int j = i; j < 128; j += 32) {
            int w = 1 + 700 * j;  // always odd, < NN words
            nz_e |= (ei[w] != 0);
            nz_b |= (bat[w] != 0);
        }
        unsigned be = __ballot_sync(0xffffffffu, nz_e);
        unsigned bb = __ballot_sync(0xffffffffu, nz_b);
        if (i == 0) {
            g_is64_edge = (be == 0);
            g_is64_batch = (bb == 0);
        }
    }
}

// ---------------- fused: lin0 GEMM (fp32, R7 schedule) + degree histogram ----
// Edge blocks: 4 edges/thread, loads batched (MLP 4) before the atomic phase.
__global__ void fused_lin0_deg(const float* __restrict__ A, const float* __restrict__ W,
                               const float* __restrict__ biasC, float* __restrict__ C,
                               const void* ei, const float* __restrict__ ew,
                               int gemm_blocks) {
    __shared__ float Ws[FIN * D];
    __shared__ float As[20 * APAD];
    int tid = threadIdx.x;

    if (blockIdx.x >= gemm_blocks) {
        int base = (blockIdx.x - gemm_blocks) * 1024 + tid;
        int is64 = g_is64_edge;
        int c[4]; float w[4];
#pragma unroll
        for (int j = 0; j < 4; j++) {
            int e = base + j * 256;
            if (e < EE) {
                c[j] = load_idx(ei, (long long)EE + e, is64);
                w[j] = ew[e];
            } else c[j] = -1;
        }
#pragma unroll
        for (int j = 0; j < 4; j++) {
            if (c[j] >= 0) {
                atomicAdd(&g_deg[c[j]], w[j]);
                atomicAdd(&g_cntn[c[j]], 1);
            }
        }
        return;
    }

    int row0 = blockIdx.x * 128;
    for (int i = tid; i < FIN * D; i += 256) Ws[i] = W[i];
    int tx = tid & 15, ty = tid >> 4;
    float acc[8][4] = {};

    for (int kb = 0; kb < FIN; kb += 20) {
        __syncthreads();  // also guards Ws on first iteration
        for (int i = tid; i < 128 * 20; i += 256) {
            int rr = i / 20, kk = i - rr * 20;
            int r = row0 + rr;
            As[kk * APAD + rr] = (r < NN) ? A[(long long)r * FIN + kb + kk] : 0.f;
        }
        __syncthreads();
#pragma unroll
        for (int k = 0; k < 20; k++) {
            float4 a0 = *(const float4*)&As[k * APAD + ty * 8];
            float4 a1 = *(const float4*)&As[k * APAD + ty * 8 + 4];
            float4 wv = *(const float4*)&Ws[(kb + k) * D + tx * 4];
            float av[8] = {a0.x, a0.y, a0.z, a0.w, a1.x, a1.y, a1.z, a1.w};
#pragma unroll
            for (int i2 = 0; i2 < 8; i2++) {
                acc[i2][0] += av[i2] * wv.x;
                acc[i2][1] += av[i2] * wv.y;
                acc[i2][2] += av[i2] * wv.z;
                acc[i2][3] += av[i2] * wv.w;
            }
        }
    }
    int c0 = tx * 4;
    float4 bc = *(const float4*)&biasC[c0];
#pragma unroll
    for (int i2 = 0; i2 < 8; i2++) {
        int r = row0 + ty * 8 + i2;
        if (r >= NN) break;
        float4 v = make_float4(fmaxf(acc[i2][0] + bc.x, 0.f), fmaxf(acc[i2][1] + bc.y, 0.f),
                               fmaxf(acc[i2][2] + bc.z, 0.f), fmaxf(acc[i2][3] + bc.w, 0.f));
        *(float4*)&C[(long long)r * D + c0] = v;
    }
}

// ---------------- two-level exclusive scan over g_cntn -> g_ptr --------------
__global__ void scan1_kernel() {
    __shared__ int sh[SCAN_T];
    int tid = threadIdx.x;
    int i = blockIdx.x * SCAN_T + tid;
    int v = (i < NN) ? g_cntn[i] : 0;
    sh[tid] = v;
    __syncthreads();
    for (int off = 1; off < SCAN_T; off <<= 1) {
        int t = (tid >= off) ? sh[tid - off] : 0;
        __syncthreads();
        sh[tid] += t;
        __syncthreads();
    }
    if (i < NN) g_ptr[i] = sh[tid] - v;  // exclusive (local)
    if (tid == SCAN_T - 1) g_partials[blockIdx.x] = sh[tid];
}

__global__ void scan2_kernel() {  // 1 block of 256 (SCAN_NB=196 < 256)
    __shared__ int sh[256];
    int tid = threadIdx.x;
    int v = (tid < SCAN_NB) ? g_partials[tid] : 0;
    sh[tid] = v;
    __syncthreads();
    for (int off = 1; off < 256; off <<= 1) {
        int t = (tid >= off) ? sh[tid - off] : 0;
        __syncthreads();
        sh[tid] += t;
        __syncthreads();
    }
    if (tid < SCAN_NB) g_partials[tid] = sh[tid] - v;  // exclusive
}

// ---------------- conv GEMM (fp32, fp16 out, swizzled As) + fused scatter ----
// Scatter blocks: 4 edges/thread; idx/weight/deg/ptr loads all batched (MLP 8)
// before the atomic+store phase.
// As staging stores XOR-swizzled (rr ^ ((kk>>3)&3)*8) -> conflict-free.
template <bool DO_SCATTER>
__global__ void gemm_conv(const float* __restrict__ A, const float* __restrict__ W,
                          unsigned* __restrict__ hout, int nrows,
                          const void* ei, const float* __restrict__ ew,
                          int gemm_blocks) {
    __shared__ float Ws[D * D];
    __shared__ float As[32 * APAD];

    int tid = threadIdx.x;
    if (DO_SCATTER && blockIdx.x >= gemm_blocks) {
        int base = (blockIdx.x - gemm_blocks) * 1024 + tid;
        int is64 = g_is64_edge;
        int r[4], c[4]; float w[4];
#pragma unroll
        for (int j = 0; j < 4; j++) {
            int e = base + j * 256;
            if (e < EE) {
                r[j] = load_idx(ei, e, is64);
                c[j] = load_idx(ei, (long long)EE + e, is64);
                w[j] = ew[e];
            } else c[j] = -1;
        }
        float dr[4], dc[4]; int pp[4];
#pragma unroll
        for (int j = 0; j < 4; j++) {
            if (c[j] >= 0) {
                dr[j] = g_deg[r[j]];
                dc[j] = g_deg[c[j]];
                pp[j] = g_ptr[c[j]] + g_partials[c[j] >> 9];
            }
        }
#pragma unroll
        for (int j = 0; j < 4; j++) {
            if (c[j] >= 0) {
                float ir = dr[j] > 0.f ? rsqrtf(dr[j]) : 0.f;
                float ic = dc[j] > 0.f ? rsqrtf(dc[j]) : 0.f;
                int old = atomicSub(&g_cntn[c[j]], 1);
                g_csr[pp[j] + old - 1] = make_int2(r[j], __float_as_int(ir * w[j] * ic));
            }
        }
        return;
    }

    int row0 = blockIdx.x * 128;
    for (int i = tid; i < D * D; i += 256) Ws[i] = W[i];
    int tx = tid & 15, ty = tid >> 4;
    float acc[8][4] = {};

    for (int kb = 0; kb < D; kb += 32) {
        __syncthreads();
        for (int i = tid; i < 128 * 32; i += 256) {
            int rr = i >> 5, kk = i & 31;
            int r = row0 + rr;
            float v = (r < nrows) ? A[(long long)r * D + kb + kk] : 0.f;
            As[kk * APAD + (rr ^ (((kk >> 3) & 3) << 3))] = v;
        }
        __syncthreads();
#pragma unroll
        for (int k = 0; k < 32; k++) {
            int tys = (ty ^ ((k >> 3) & 3)) * 8;
            float4 a0 = *(const float4*)&As[k * APAD + tys];
            float4 a1 = *(const float4*)&As[k * APAD + tys + 4];
            float4 wv = *(const float4*)&Ws[(kb + k) * D + tx * 4];
            float av[8] = {a0.x, a0.y, a0.z, a0.w, a1.x, a1.y, a1.z, a1.w};
#pragma unroll
            for (int i2 = 0; i2 < 8; i2++) {
                acc[i2][0] += av[i2] * wv.x;
                acc[i2][1] += av[i2] * wv.y;
                acc[i2][2] += av[i2] * wv.z;
                acc[i2][3] += av[i2] * wv.w;
            }
        }
    }

#pragma unroll
    for (int i2 = 0; i2 < 8; i2++) {
        int r = row0 + ty * 8 + i2;
        if (r >= nrows) break;
        __half2 ha = __floats2half2_rn(acc[i2][0], acc[i2][1]);
        __half2 hb = __floats2half2_rn(acc[i2][2], acc[i2][3]);
        uint2 u;
        u.x = *(unsigned*)&ha;
        u.y = *(unsigned*)&hb;
        ((uint2*)hout)[(long long)r * 16 + tx] = u;
    }
}

// ---------------- CSR aggregation core: 4x unrolled, 16 edges in flight ------
__device__ __forceinline__ void agg_accum(float acc[8], uint4 u, float nv) {
    __half2* hh = (__half2*)&u;
#pragma unroll
    for (int c = 0; c < 4; c++) {
        float2 f = __half22float2(hh[c]);
        acc[2 * c]     += f.x * nv;
        acc[2 * c + 1] += f.y * nv;
    }
}

__device__ __forceinline__ void agg_core(int node, const uint4* __restrict__ h,
                                         int q, int p, float acc[8]) {
    int s = ptr_of(node), e = ptr_of(node + 1);
    int i = s + q;
    for (; i + 12 < e; i += 16) {
        int2 e0 = g_csr[i];
        int2 e1 = g_csr[i + 4];
        int2 e2 = g_csr[i + 8];
        int2 e3 = g_csr[i + 12];
        uint4 u0 = h[e0.x * 8 + p];
        uint4 u1 = h[e1.x * 8 + p];
        uint4 u2 = h[e2.x * 8 + p];
        uint4 u3 = h[e3.x * 8 + p];
        agg_accum(acc, u0, __int_as_float(e0.y));
        agg_accum(acc, u1, __int_as_float(e1.y));
        agg_accum(acc, u2, __int_as_float(e2.y));
        agg_accum(acc, u3, __int_as_float(e3.y));
    }
    if (i + 4 < e) {
        int2 e0 = g_csr[i];
        int2 e1 = g_csr[i + 4];
        uint4 u0 = h[e0.x * 8 + p];
        uint4 u1 = h[e1.x * 8 + p];
        agg_accum(acc, u0, __int_as_float(e0.y));
        agg_accum(acc, u1, __int_as_float(e1.y));
        i += 8;
    }
    if (i < e) {
        int2 e0 = g_csr[i];
        uint4 u0 = h[e0.x * 8 + p];
        agg_accum(acc, u0, __int_as_float(e0.y));
    }
#pragma unroll
    for (int c = 0; c < 8; c++) {
        acc[c] += __shfl_xor_sync(0xffffffffu, acc[c], 8);
        acc[c] += __shfl_xor_sync(0xffffffffu, acc[c], 16);
    }
}

__global__ void agg_half(const uint4* __restrict__ h,
                         const float* __restrict__ bias, float* __restrict__ outp) {
    int node = (blockIdx.x * blockDim.x + threadIdx.x) >> 5;
    if (node >= NN) return;
    int lane = threadIdx.x & 31;
    int q = lane >> 3, p = lane & 7;
    float acc[8] = {};
    agg_core(node, h, q, p, acc);
    if (q == 0) {
        float4 b0 = *(const float4*)&bias[8 * p];
        float4 b1 = *(const float4*)&bias[8 * p + 4];
        float4 o0 = make_float4(fmaxf(acc[0] + b0.x, 0.f), fmaxf(acc[1] + b0.y, 0.f),
                                fmaxf(acc[2] + b0.z, 0.f), fmaxf(acc[3] + b0.w, 0.f));
        float4 o1 = make_float4(fmaxf(acc[4] + b1.x, 0.f), fmaxf(acc[5] + b1.y, 0.f),
                                fmaxf(acc[6] + b1.z, 0.f), fmaxf(acc[7] + b1.w, 0.f));
        float* row = outp + (long long)node * D + 8 * p;
        *(float4*)row = o0;
        *(float4*)(row + 4) = o1;
    }
}

__device__ __forceinline__ void red_add_v4(float4* addr, float4 v) {
    asm volatile("red.global.add.v4.f32 [%0], {%1,%2,%3,%4};"
                 :: "l"(addr), "f"(v.x), "f"(v.y), "f"(v.z), "f"(v.w)
                 : "memory");
}

// Last layer: aggregate + bias + relu + mean-pool accumulate.
__global__ void agg_pool(const uint4* __restrict__ h,
                         const float* __restrict__ bias, const void* batch) {
    int node = (blockIdx.x * blockDim.x + threadIdx.x) >> 5;
    if (node >= NN) return;
    int lane = threadIdx.x & 31;
    int q = lane >> 3, p = lane & 7;
    float acc[8] = {};
    agg_core(node, h, q, p, acc);
    if (q == 0) {
        int g = load_idx(batch, node, g_is64_batch);
        float4 b0 = *(const float4*)&bias[8 * p];
        float4 b1 = *(const float4*)&bias[8 * p + 4];
        float4 o0 = make_float4(fmaxf(acc[0] + b0.x, 0.f), fmaxf(acc[1] + b0.y, 0.f),
                                fmaxf(acc[2] + b0.z, 0.f), fmaxf(acc[3] + b0.w, 0.f));
        float4 o1 = make_float4(fmaxf(acc[4] + b1.x, 0.f), fmaxf(acc[5] + b1.y, 0.f),
                                fmaxf(acc[6] + b1.z, 0.f), fmaxf(acc[7] + b1.w, 0.f));
        float* row = g_sums + g * D + 8 * p;
        red_add_v4((float4*)row, o0);
        red_add_v4((float4*)(row + 4), o1);
        if (p == 0) atomicAdd(&g_cnt[g], 1.0f);
    }
}

// ---------------- fused MLP tail: lin1 -> fc0 -> fc1 -> lin2 ----------------
__global__ void tail_kernel(const float* __restrict__ W1, const float* __restrict__ b1,
                            const float* __restrict__ fcw, const float* __restrict__ fcb,
                            const float* __restrict__ w2, const float* __restrict__ b2,
                            float* __restrict__ out) {
    int g = blockIdx.x, tid = threadIdx.x;  // 64 threads
    __shared__ float buf[2][64];
    __shared__ float red[64];

    buf[0][tid] = g_sums[g * D + tid] / fmaxf(g_cnt[g], 1.f);
    __syncthreads();
    {
        float acc = 0.f;
#pragma unroll
        for (int k = 0; k < 64; k++) acc += buf[0][k] * W1[k * D + tid];
        buf[1][tid] = fmaxf(acc + b1[tid], 0.f);
        __syncthreads();
    }
    int cur = 1;
    for (int L = 0; L < 2; L++) {
        const float* W = fcw + L * D * D;
        float acc = 0.f;
#pragma unroll
        for (int k = 0; k < 64; k++) acc += buf[cur][k] * W[k * D + tid];
        __syncthreads();
        buf[cur ^ 1][tid] = fmaxf(acc + fcb[L * D + tid], 0.f);
        cur ^= 1;
        __syncthreads();
    }
    red[tid] = buf[cur][tid] * w2[tid];
    __syncthreads();
    if (tid < 32) {
        float s = red[tid] + red[tid + 32];
#pragma unroll
        for (int off = 16; off; off >>= 1) s += __shfl_down_sync(0xffffffffu, s, off);
        if (tid == 0) out[g] = s + b2[0];
    }
}

// ---------------- launch ----------------
extern "C" void kernel_launch(void* const* d_in, const int* in_sizes, int n_in,
                              void* d_out, int out_size) {
    const float* x      = (const float*)d_in[0];
    const void*  ei     = d_in[1];
    const float* ew     = (const float*)d_in[2];
    const void*  batch  = d_in[3];
    const float* lin0_w = (const float*)d_in[4];
    const float* lin0_b = (const float*)d_in[5];
    const float* conv_w = (const float*)d_in[6];
    const float* conv_b = (const float*)d_in[7];
    const float* lin1_w = (const float*)d_in[8];
    const float* lin1_b = (const float*)d_in[9];
    const float* fc_w   = (const float*)d_in[10];
    const float* fc_b   = (const float*)d_in[11];
    const float* lin2_w = (const float*)d_in[12];
    const float* lin2_b = (const float*)d_in[13];
    float* out = (float*)d_out;

    float *p_out0, *p_aggA, *p_aggB;
    uint4* p_h;
    cudaGetSymbolAddress((void**)&p_out0, g_out0);
    cudaGetSymbolAddress((void**)&p_h,    g_hh);
    cudaGetSymbolAddress((void**)&p_aggA, g_aggA);
    cudaGetSymbolAddress((void**)&p_aggB, g_aggB);

    // init: zero deg/cntn/sums/cnt + dtype detect
    init_kernel<<<(NN + 255) / 256, 256>>>((const int*)ei, (const int*)batch);

    // fused lin0 GEMM + degree histogram (overlapped, 4 edges/thread)
    const int GB = (NN + 127) / 128;            // 782 gemm blocks
    const int DB4 = (EE + 1023) / 1024;         // 1563 edge blocks
    fused_lin0_deg<<<GB + DB4, 256>>>(x, lin0_w, lin0_b, p_out0, ei, ew, GB);

    scan1_kernel<<<SCAN_NB, SCAN_T>>>();
    scan2_kernel<<<1, 256>>>();

    float* bufs[2] = {p_aggA, p_aggB};
    const float* Ain = p_out0;
    const int AGB = (NN * 32) / 256;  // 12500 blocks
    for (int i = 0; i < 4; i++) {
        if (i == 0) {
            // conv-0 GEMM fused with CSR scatter (overlapped, 4 edges/thread)
            gemm_conv<true><<<GB + DB4, 256>>>(Ain, conv_w, (unsigned*)p_h, NN, ei, ew, GB);
        } else {
            gemm_conv<false><<<GB, 256>>>(Ain, conv_w + i * D * D, (unsigned*)p_h, NN,
                                          ei, ew, GB);
        }
        if (i < 3) {
            float* agg = bufs[i & 1];
            agg_half<<<AGB, 256>>>(p_h, conv_b + i * D, agg);
            Ain = agg;
        } else {
            agg_pool<<<AGB, 256>>>(p_h, conv_b + i * D, batch);
        }
    }

    tail_kernel<<<GG, 64>>>(lin1_w, lin1_b, fc_w, fc_b, lin2_w, lin2_b, out);
}

// round 13
// speedup vs baseline: 1.0051x; 1.0051x over previous
#include <cuda_runtime.h>
#include <cuda_fp16.h>

#define NN 100000
#define EE 1600000
#define FIN 100
#define D 64
#define GG 500
#define SCAN_T 512
#define SCAN_NB ((NN + SCAN_T - 1) / SCAN_T)
#define APAD 132

// ---------------- scratch (device globals; no allocs allowed) ----------------
__device__ float g_deg[NN];
__device__ int   g_cntn[NN];
__device__ int   g_ptr[NN + 1];
__device__ int   g_partials[SCAN_NB];
__device__ int2  g_csr[EE];        // packed {row, norm_bits}
__device__ float g_out0[NN * D];
__device__ uint4 g_hh[NN * 8];     // h fp16: 64 halves = 8 uint4 per row
__device__ float g_aggA[NN * D];
__device__ float g_aggB[NN * D];
__device__ float g_sums[GG * D];
__device__ float g_cnt[GG];
__device__ int g_is64_edge;
__device__ int g_is64_batch;
__device__ int g_scan_ctr;
__device__ int g_scan_done;

__device__ __forceinline__ int load_idx(const void* p, long long i, int is64) {
    return is64 ? (int)((const long long*)p)[i] : ((const int*)p)[i];
}

// ptr fixup inlined: final ptr(n) = g_ptr[n] + partials[n>>9]
__device__ __forceinline__ int ptr_of(int n) {
    return (n == NN) ? EE : g_ptr[n] + g_partials[n >> 9];
}

// ---------------- init: zero scratch + dtype detect (one kernel) -------------
__global__ void init_kernel(const int* ei, const int* bat) {
    int t = blockIdx.x * 256 + threadIdx.x;
    if (t < NN) { g_deg[t] = 0.f; g_cntn[t] = 0; }
    if (t < GG * D) g_sums[t] = 0.f;
    if (t < GG) g_cnt[t] = 0.f;
    if (t == 0) { g_scan_ctr = 0; g_scan_done = 0; }
    if (blockIdx.x == 0 && threadIdx.x < 32) {
        int i = threadIdx.x;
        int nz_e = 0, nz_b = 0;
        for (int j = i; j < 128; j += 32) {
            int w = 1 + 700 * j;  // always odd, < NN words
            nz_e |= (ei[w] != 0);
            nz_b |= (bat[w] != 0);
        }
        unsigned be = __ballot_sync(0xffffffffu, nz_e);
        unsigned bb = __ballot_sync(0xffffffffu, nz_b);
        if (i == 0) {
            g_is64_edge = (be == 0);
            g_is64_batch = (bb == 0);
        }
    }
}

// ---------------- fused: lin0 GEMM (fp32, R7 schedule) + degree histogram ----
__global__ void fused_lin0_deg(const float* __restrict__ A, const float* __restrict__ W,
                               const float* __restrict__ biasC, float* __restrict__ C,
                               const void* ei, const float* __restrict__ ew,
                               int gemm_blocks) {
    __shared__ float Ws[FIN * D];
    __shared__ float As[20 * APAD];
    int tid = threadIdx.x;

    if (blockIdx.x >= gemm_blocks) {
        int base = (blockIdx.x - gemm_blocks) * 1024 + tid;
        int is64 = g_is64_edge;
        int c[4]; float w[4];
#pragma unroll
        for (int j = 0; j < 4; j++) {
            int e = base + j * 256;
            if (e < EE) {
                c[j] = load_idx(ei, (long long)EE + e, is64);
                w[j] = ew[e];
            } else c[j] = -1;
        }
#pragma unroll
        for (int j = 0; j < 4; j++) {
            if (c[j] >= 0) {
                atomicAdd(&g_deg[c[j]], w[j]);
                atomicAdd(&g_cntn[c[j]], 1);
            }
        }
        return;
    }

    int row0 = blockIdx.x * 128;
    for (int i = tid; i < FIN * D; i += 256) Ws[i] = W[i];
    int tx = tid & 15, ty = tid >> 4;
    float acc[8][4] = {};

    for (int kb = 0; kb < FIN; kb += 20) {
        __syncthreads();  // also guards Ws on first iteration
        for (int i = tid; i < 128 * 20; i += 256) {
            int rr = i / 20, kk = i - rr * 20;
            int r = row0 + rr;
            As[kk * APAD + rr] = (r < NN) ? A[(long long)r * FIN + kb + kk] : 0.f;
        }
        __syncthreads();
#pragma unroll
        for (int k = 0; k < 20; k++) {
            float4 a0 = *(const float4*)&As[k * APAD + ty * 8];
            float4 a1 = *(const float4*)&As[k * APAD + ty * 8 + 4];
            float4 wv = *(const float4*)&Ws[(kb + k) * D + tx * 4];
            float av[8] = {a0.x, a0.y, a0.z, a0.w, a1.x, a1.y, a1.z, a1.w};
#pragma unroll
            for (int i2 = 0; i2 < 8; i2++) {
                acc[i2][0] += av[i2] * wv.x;
                acc[i2][1] += av[i2] * wv.y;
                acc[i2][2] += av[i2] * wv.z;
                acc[i2][3] += av[i2] * wv.w;
            }
        }
    }
    int c0 = tx * 4;
    float4 bc = *(const float4*)&biasC[c0];
#pragma unroll
    for (int i2 = 0; i2 < 8; i2++) {
        int r = row0 + ty * 8 + i2;
        if (r >= NN) break;
        float4 v = make_float4(fmaxf(acc[i2][0] + bc.x, 0.f), fmaxf(acc[i2][1] + bc.y, 0.f),
                               fmaxf(acc[i2][2] + bc.z, 0.f), fmaxf(acc[i2][3] + bc.w, 0.f));
        *(float4*)&C[(long long)r * D + c0] = v;
    }
}

// ---------------- mega kernel: [scan | conv0 GEMM | scatter] in one launch ---
// scan blocks: two-level exclusive scan with decoupled last-block phase 2.
// gemm blocks: conv-0 GEMM (fp32 in, fp16 out), no dependency on scan.
// scatter blocks: spin on g_scan_done, then build packed CSR (4 edges/thread).
__global__ void mega_conv0(const float* __restrict__ A, const float* __restrict__ W,
                           unsigned* __restrict__ hout,
                           const void* ei, const float* __restrict__ ew,
                           int gemm_blocks) {
    __shared__ float Ws[D * D];
    __shared__ float As[32 * APAD];
    __shared__ int sh[256];
    __shared__ int is_last;
    int tid = threadIdx.x;
    int bid = blockIdx.x;

    if (bid < SCAN_NB) {
        // ---- scan phase 1: 512 elements per block, 2 per thread ----
        int i0 = bid * SCAN_T + 2 * tid;
        int a = (i0 < NN) ? g_cntn[i0] : 0;
        int b = (i0 + 1 < NN) ? g_cntn[i0 + 1] : 0;
        sh[tid] = a + b;
        __syncthreads();
        for (int off = 1; off < 256; off <<= 1) {
            int t = (tid >= off) ? sh[tid - off] : 0;
            __syncthreads();
            sh[tid] += t;
            __syncthreads();
        }
        int excl = sh[tid] - (a + b);
        if (i0 < NN) g_ptr[i0] = excl;
        if (i0 + 1 < NN) g_ptr[i0 + 1] = excl + a;
        if (tid == 255) {
            g_partials[bid] = sh[255];
            __threadfence();
            int t = atomicAdd(&g_scan_ctr, 1);
            is_last = (t == SCAN_NB - 1);
        }
        __syncthreads();
        if (!is_last) return;
        // ---- scan phase 2 (last block): exclusive scan over g_partials ----
        int v = (tid < SCAN_NB) ? *(volatile int*)&g_partials[tid] : 0;
        sh[tid] = v;
        __syncthreads();
        for (int off = 1; off < 256; off <<= 1) {
            int t = (tid >= off) ? sh[tid - off] : 0;
            __syncthreads();
            sh[tid] += t;
            __syncthreads();
        }
        if (tid < SCAN_NB) g_partials[tid] = sh[tid] - v;  // exclusive
        __threadfence();
        __syncthreads();
        if (tid == 0) atomicExch(&g_scan_done, 1);
        return;
    }

    if (bid < SCAN_NB + gemm_blocks) {
        // ---- conv-0 GEMM ----
        int gb = bid - SCAN_NB;
        int row0 = gb * 128;
        for (int i = tid; i < D * D; i += 256) Ws[i] = W[i];
        int tx = tid & 15, ty = tid >> 4;
        float acc[8][4] = {};

        for (int kb = 0; kb < D; kb += 32) {
            __syncthreads();
            for (int i = tid; i < 128 * 32; i += 256) {
                int rr = i >> 5, kk = i & 31;
                int r = row0 + rr;
                float v = (r < NN) ? A[(long long)r * D + kb + kk] : 0.f;
                As[kk * APAD + (rr ^ (((kk >> 3) & 3) << 3))] = v;
            }
            __syncthreads();
#pragma unroll
            for (int k = 0; k < 32; k++) {
                int tys = (ty ^ ((k >> 3) & 3)) * 8;
                float4 a0 = *(const float4*)&As[k * APAD + tys];
                float4 a1 = *(const float4*)&As[k * APAD + tys + 4];
                float4 wv = *(const float4*)&Ws[(kb + k) * D + tx * 4];
                float av[8] = {a0.x, a0.y, a0.z, a0.w, a1.x, a1.y, a1.z, a1.w};
#pragma unroll
                for (int i2 = 0; i2 < 8; i2++) {
                    acc[i2][0] += av[i2] * wv.x;
                    acc[i2][1] += av[i2] * wv.y;
                    acc[i2][2] += av[i2] * wv.z;
                    acc[i2][3] += av[i2] * wv.w;
                }
            }
        }
#pragma unroll
        for (int i2 = 0; i2 < 8; i2++) {
            int r = row0 + ty * 8 + i2;
            if (r >= NN) break;
            __half2 ha = __floats2half2_rn(acc[i2][0], acc[i2][1]);
            __half2 hb = __floats2half2_rn(acc[i2][2], acc[i2][3]);
            uint2 u;
            u.x = *(unsigned*)&ha;
            u.y = *(unsigned*)&hb;
            ((uint2*)hout)[(long long)r * 16 + tx] = u;
        }
        return;
    }

    // ---- scatter: wait for scan completion, then build CSR ----
    if (tid == 0) {
        while (atomicAdd(&g_scan_done, 0) == 0) __nanosleep(64);
    }
    __syncthreads();
    {
        int base = (bid - SCAN_NB - gemm_blocks) * 1024 + tid;
        int is64 = g_is64_edge;
        int r[4], c[4]; float w[4];
#pragma unroll
        for (int j = 0; j < 4; j++) {
            int e = base + j * 256;
            if (e < EE) {
                r[j] = load_idx(ei, e, is64);
                c[j] = load_idx(ei, (long long)EE + e, is64);
                w[j] = ew[e];
            } else c[j] = -1;
        }
        float dr[4], dc[4]; int pp[4];
#pragma unroll
        for (int j = 0; j < 4; j++) {
            if (c[j] >= 0) {
                dr[j] = g_deg[r[j]];
                dc[j] = g_deg[c[j]];
                pp[j] = g_ptr[c[j]] + g_partials[c[j] >> 9];
            }
        }
#pragma unroll
        for (int j = 0; j < 4; j++) {
            if (c[j] >= 0) {
                float ir = dr[j] > 0.f ? rsqrtf(dr[j]) : 0.f;
                float ic = dc[j] > 0.f ? rsqrtf(dc[j]) : 0.f;
                int old = atomicSub(&g_cntn[c[j]], 1);
                g_csr[pp[j] + old - 1] = make_int2(r[j], __float_as_int(ir * w[j] * ic));
            }
        }
    }
}

// ---------------- conv GEMM layers 1..3 (fp32, fp16 out, swizzled As) --------
__global__ void gemm_conv(const float* __restrict__ A, const float* __restrict__ W,
                          unsigned* __restrict__ hout, int nrows) {
    __shared__ float Ws[D * D];
    __shared__ float As[32 * APAD];

    int tid = threadIdx.x;
    int row0 = blockIdx.x * 128;
    for (int i = tid; i < D * D; i += 256) Ws[i] = W[i];
    int tx = tid & 15, ty = tid >> 4;
    float acc[8][4] = {};

    for (int kb = 0; kb < D; kb += 32) {
        __syncthreads();
        for (int i = tid; i < 128 * 32; i += 256) {
            int rr = i >> 5, kk = i & 31;
            int r = row0 + rr;
            float v = (r < nrows) ? A[(long long)r * D + kb + kk] : 0.f;
            As[kk * APAD + (rr ^ (((kk >> 3) & 3) << 3))] = v;
        }
        __syncthreads();
#pragma unroll
        for (int k = 0; k < 32; k++) {
            int tys = (ty ^ ((k >> 3) & 3)) * 8;
            float4 a0 = *(const float4*)&As[k * APAD + tys];
            float4 a1 = *(const float4*)&As[k * APAD + tys + 4];
            float4 wv = *(const float4*)&Ws[(kb + k) * D + tx * 4];
            float av[8] = {a0.x, a0.y, a0.z, a0.w, a1.x, a1.y, a1.z, a1.w};
#pragma unroll
            for (int i2 = 0; i2 < 8; i2++) {
                acc[i2][0] += av[i2] * wv.x;
                acc[i2][1] += av[i2] * wv.y;
                acc[i2][2] += av[i2] * wv.z;
                acc[i2][3] += av[i2] * wv.w;
            }
        }
    }

#pragma unroll
    for (int i2 = 0; i2 < 8; i2++) {
        int r = row0 + ty * 8 + i2;
        if (r >= nrows) break;
        __half2 ha = __floats2half2_rn(acc[i2][0], acc[i2][1]);
        __half2 hb = __floats2half2_rn(acc[i2][2], acc[i2][3]);
        uint2 u;
        u.x = *(unsigned*)&ha;
        u.y = *(unsigned*)&hb;
        ((uint2*)hout)[(long long)r * 16 + tx] = u;
    }
}

// ---------------- CSR aggregation core: 4x unrolled, 16 edges in flight ------
__device__ __forceinline__ void agg_accum(float acc[8], uint4 u, float nv) {
    __half2* hh = (__half2*)&u;
#pragma unroll
    for (int c = 0; c < 4; c++) {
        float2 f = __half22float2(hh[c]);
        acc[2 * c]     += f.x * nv;
        acc[2 * c + 1] += f.y * nv;
    }
}

__device__ __forceinline__ void agg_core(int node, const uint4* __restrict__ h,
                                         int q, int p, float acc[8]) {
    int s = ptr_of(node), e = ptr_of(node + 1);
    int i = s + q;
    for (; i + 12 < e; i += 16) {
        int2 e0 = g_csr[i];
        int2 e1 = g_csr[i + 4];
        int2 e2 = g_csr[i + 8];
        int2 e3 = g_csr[i + 12];
        uint4 u0 = h[e0.x * 8 + p];
        uint4 u1 = h[e1.x * 8 + p];
        uint4 u2 = h[e2.x * 8 + p];
        uint4 u3 = h[e3.x * 8 + p];
        agg_accum(acc, u0, __int_as_float(e0.y));
        agg_accum(acc, u1, __int_as_float(e1.y));
        agg_accum(acc, u2, __int_as_float(e2.y));
        agg_accum(acc, u3, __int_as_float(e3.y));
    }
    if (i + 4 < e) {
        int2 e0 = g_csr[i];
        int2 e1 = g_csr[i + 4];
        uint4 u0 = h[e0.x * 8 + p];
        uint4 u1 = h[e1.x * 8 + p];
        agg_accum(acc, u0, __int_as_float(e0.y));
        agg_accum(acc, u1, __int_as_float(e1.y));
        i += 8;
    }
    if (i < e) {
        int2 e0 = g_csr[i];
        uint4 u0 = h[e0.x * 8 + p];
        agg_accum(acc, u0, __int_as_float(e0.y));
    }
#pragma unroll
    for (int c = 0; c < 8; c++) {
        acc[c] += __shfl_xor_sync(0xffffffffu, acc[c], 8);
        acc[c] += __shfl_xor_sync(0xffffffffu, acc[c], 16);
    }
}

__global__ void agg_half(const uint4* __restrict__ h,
                         const float* __restrict__ bias, float* __restrict__ outp) {
    int node = (blockIdx.x * blockDim.x + threadIdx.x) >> 5;
    if (node >= NN) return;
    int lane = threadIdx.x & 31;
    int q = lane >> 3, p = lane & 7;
    float acc[8] = {};
    agg_core(node, h, q, p, acc);
    if (q == 0) {
        float4 b0 = *(const float4*)&bias[8 * p];
        float4 b1 = *(const float4*)&bias[8 * p + 4];
        float4 o0 = make_float4(fmaxf(acc[0] + b0.x, 0.f), fmaxf(acc[1] + b0.y, 0.f),
                                fmaxf(acc[2] + b0.z, 0.f), fmaxf(acc[3] + b0.w, 0.f));
        float4 o1 = make_float4(fmaxf(acc[4] + b1.x, 0.f), fmaxf(acc[5] + b1.y, 0.f),
                                fmaxf(acc[6] + b1.z, 0.f), fmaxf(acc[7] + b1.w, 0.f));
        float* row = outp + (long long)node * D + 8 * p;
        *(float4*)row = o0;
        *(float4*)(row + 4) = o1;
    }
}

__device__ __forceinline__ void red_add_v4(float4* addr, float4 v) {
    asm volatile("red.global.add.v4.f32 [%0], {%1,%2,%3,%4};"
                 :: "l"(addr), "f"(v.x), "f"(v.y), "f"(v.z), "f"(v.w)
                 : "memory");
}

// Last layer: aggregate + bias + relu + mean-pool accumulate.
__global__ void agg_pool(const uint4* __restrict__ h,
                         const float* __restrict__ bias, const void* batch) {
    int node = (blockIdx.x * blockDim.x + threadIdx.x) >> 5;
    if (node >= NN) return;
    int lane = threadIdx.x & 31;
    int q = lane >> 3, p = lane & 7;
    float acc[8] = {};
    agg_core(node, h, q, p, acc);
    if (q == 0) {
        int g = load_idx(batch, node, g_is64_batch);
        float4 b0 = *(const float4*)&bias[8 * p];
        float4 b1 = *(const float4*)&bias[8 * p + 4];
        float4 o0 = make_float4(fmaxf(acc[0] + b0.x, 0.f), fmaxf(acc[1] + b0.y, 0.f),
                                fmaxf(acc[2] + b0.z, 0.f), fmaxf(acc[3] + b0.w, 0.f));
        float4 o1 = make_float4(fmaxf(acc[4] + b1.x, 0.f), fmaxf(acc[5] + b1.y, 0.f),
                                fmaxf(acc[6] + b1.z, 0.f), fmaxf(acc[7] + b1.w, 0.f));
        float* row = g_sums + g * D + 8 * p;
        red_add_v4((float4*)row, o0);
        red_add_v4((float4*)(row + 4), o1);
        if (p == 0) atomicAdd(&g_cnt[g], 1.0f);
    }
}

// ---------------- fused MLP tail: lin1 -> fc0 -> fc1 -> lin2 ----------------
__global__ void tail_kernel(const float* __restrict__ W1, const float* __restrict__ b1,
                            const float* __restrict__ fcw, const float* __restrict__ fcb,
                            const float* __restrict__ w2, const float* __restrict__ b2,
                            float* __restrict__ out) {
    int g = blockIdx.x, tid = threadIdx.x;  // 64 threads
    __shared__ float buf[2][64];
    __shared__ float red[64];

    buf[0][tid] = g_sums[g * D + tid] / fmaxf(g_cnt[g], 1.f);
    __syncthreads();
    {
        float acc = 0.f;
#pragma unroll
        for (int k = 0; k < 64; k++) acc += buf[0][k] * W1[k * D + tid];
        buf[1][tid] = fmaxf(acc + b1[tid], 0.f);
        __syncthreads();
    }
    int cur = 1;
    for (int L = 0; L < 2; L++) {
        const float* W = fcw + L * D * D;
        float acc = 0.f;
#pragma unroll
        for (int k = 0; k < 64; k++) acc += buf[cur][k] * W[k * D + tid];
        __syncthreads();
        buf[cur ^ 1][tid] = fmaxf(acc + fcb[L * D + tid], 0.f);
        cur ^= 1;
        __syncthreads();
    }
    red[tid] = buf[cur][tid] * w2[tid];
    __syncthreads();
    if (tid < 32) {
        float s = red[tid] + red[tid + 32];
#pragma unroll
        for (int off = 16; off; off >>= 1) s += __shfl_down_sync(0xffffffffu, s, off);
        if (tid == 0) out[g] = s + b2[0];
    }
}

// ---------------- launch ----------------
extern "C" void kernel_launch(void* const* d_in, const int* in_sizes, int n_in,
                              void* d_out, int out_size) {
    const float* x      = (const float*)d_in[0];
    const void*  ei     = d_in[1];
    const float* ew     = (const float*)d_in[2];
    const void*  batch  = d_in[3];
    const float* lin0_w = (const float*)d_in[4];
    const float* lin0_b = (const float*)d_in[5];
    const float* conv_w = (const float*)d_in[6];
    const float* conv_b = (const float*)d_in[7];
    const float* lin1_w = (const float*)d_in[8];
    const float* lin1_b = (const float*)d_in[9];
    const float* fc_w   = (const float*)d_in[10];
    const float* fc_b   = (const float*)d_in[11];
    const float* lin2_w = (const float*)d_in[12];
    const float* lin2_b = (const float*)d_in[13];
    float* out = (float*)d_out;

    float *p_out0, *p_aggA, *p_aggB;
    uint4* p_h;
    cudaGetSymbolAddress((void**)&p_out0, g_out0);
    cudaGetSymbolAddress((void**)&p_h,    g_hh);
    cudaGetSymbolAddress((void**)&p_aggA, g_aggA);
    cudaGetSymbolAddress((void**)&p_aggB, g_aggB);

    // init: zero deg/cntn/sums/cnt/scan flags + dtype detect
    init_kernel<<<(NN + 255) / 256, 256>>>((const int*)ei, (const int*)batch);

    // fused lin0 GEMM + degree histogram (overlapped, 4 edges/thread)
    const int GB = (NN + 127) / 128;            // 782 gemm blocks
    const int DB4 = (EE + 1023) / 1024;         // 1563 edge blocks
    fused_lin0_deg<<<GB + DB4, 256>>>(x, lin0_w, lin0_b, p_out0, ei, ew, GB);

    // mega: scan (196) | conv-0 GEMM (782) | scatter (1563) — one launch
    mega_conv0<<<SCAN_NB + GB + DB4, 256>>>(p_out0, conv_w, (unsigned*)p_h, ei, ew, GB);

    float* bufs[2] = {p_aggA, p_aggB};
    const int AGB = (NN * 32) / 256;  // 12500 blocks
    const float* Ain = nullptr;
    for (int i = 0; i < 4; i++) {
        if (i > 0) {
            gemm_conv<<<GB, 256>>>(Ain, conv_w + i * D * D, (unsigned*)p_h, NN);
        }
        if (i < 3) {
            float* agg = bufs[i & 1];
            agg_half<<<AGB, 256>>>(p_h, conv_b + i * D, agg);
            Ain = agg;
        } else {
            agg_pool<<<AGB, 256>>>(p_h, conv_b + i * D, batch);
        }
    }

    tail_kernel<<<GG, 64>>>(lin1_w, lin1_b, fc_w, fc_b, lin2_w, lin2_b, out);
}